// round 14
// baseline (speedup 1.0000x reference)
#include <cuda_runtime.h>
#include <math.h>
#include <stdint.h>

#define NN   100000
#define EE   400000
#define GG   2048
#define HH   256
#define H2   512
#define LLAY 5
#define AFEA 9
#define BFEA 3
#define AVOC 128
#define BVOC 16
#define BN_EPS 1e-5f

// Output layout (flattened float32), total 1,156,769 elements:
#define O_HS   0                      // head(sub)   [G,2]
#define O_HT   (2*GG)                 // head(triv)  [G,2]
#define O_SUB  (4*GG)                 // sub         [G,H]
#define O_GE   (4*GG + GG*HH)         // graph_emb   [G,H]
#define O_MASK (4*GG + 2*GG*HH)       // active_mask [N]
#define O_PEN  (4*GG + 2*GG*HH + NN)  // con_penalty scalar

// ---------------- scratch (device globals; no allocs allowed) ----------------
__device__ float g_h[(size_t)NN * HH];
__device__ float g_agg[(size_t)NN * HH];
__device__ float g_z[(size_t)NN * H2];
__device__ float g_assign[(size_t)NN * 2];
__device__ float g_sub[GG * HH];
__device__ float g_triv[GG * HH];
__device__ float g_gsum[GG * HH];
__device__ float g_cnt[GG];
__device__ float g_adj[GG * 4];
__device__ float g_pen[1];

// Pre-split tf32 hi/lo weights, SAME [K][N] layout as the source weights.
#define WOFF_W1(l) ((size_t)(l) * 131072)
#define WOFF_W2(l) (655360 + (size_t)(l) * 131072)
#define WOFF_C1   1310720
#define WTOT      1376256
__device__ uint32_t g_wh[WTOT];
__device__ uint32_t g_wl[WTOT];

// ---------------- small utilities ----------------
__device__ __forceinline__ float2 block_reduce2(float a, float b) {
    __shared__ float s0[8], s1[8];
    __shared__ float r0, r1;
    int wid = threadIdx.x >> 5, lane = threadIdx.x & 31;
#pragma unroll
    for (int o = 16; o > 0; o >>= 1) {
        a += __shfl_down_sync(0xffffffffu, a, o);
        b += __shfl_down_sync(0xffffffffu, b, o);
    }
    if (lane == 0) { s0[wid] = a; s1[wid] = b; }
    __syncthreads();
    if (wid == 0) {
        a = (lane < 8) ? s0[lane] : 0.f;
        b = (lane < 8) ? s1[lane] : 0.f;
#pragma unroll
        for (int o = 4; o > 0; o >>= 1) {
            a += __shfl_down_sync(0xffffffffu, a, o);
            b += __shfl_down_sync(0xffffffffu, b, o);
        }
        if (lane == 0) { r0 = a; r1 = b; }
    }
    __syncthreads();
    return make_float2(r0, r1);
}

__device__ __forceinline__ uint32_t f2tf32(float x) {
    uint32_t r;
    asm("cvt.rna.tf32.f32 %0, %1;" : "=r"(r) : "f"(x));
    return r;
}

__device__ __forceinline__ uint32_t smem_u32(const void* p) {
    uint32_t a;
    asm("{ .reg .u64 t; cvta.to.shared.u64 t, %1; cvt.u32.u64 %0, t; }" : "=r"(a) : "l"(p));
    return a;
}

__device__ __forceinline__ void cp_async16(uint32_t dst, const void* src) {
    asm volatile("cp.async.ca.shared.global [%0], [%1], 16;" :: "r"(dst), "l"(src) : "memory");
}
#define CP_COMMIT() asm volatile("cp.async.commit_group;" ::: "memory")
#define CP_WAIT0()  asm volatile("cp.async.wait_group 0;" ::: "memory")

__device__ __forceinline__ void mma_tf32(float* d, const uint32_t* a, uint32_t b0, uint32_t b1) {
    asm volatile("mma.sync.aligned.m16n8k8.row.col.f32.tf32.tf32.f32 "
                 "{%0,%1,%2,%3}, {%4,%5,%6,%7}, {%8,%9}, {%0,%1,%2,%3};"
                 : "+f"(d[0]), "+f"(d[1]), "+f"(d[2]), "+f"(d[3])
                 : "r"(a[0]), "r"(a[1]), "r"(a[2]), "r"(a[3]), "r"(b0), "r"(b1));
}

// ---------------- misc kernels ----------------

__global__ __launch_bounds__(256) void zero_k() {
    int i = blockIdx.x * 256 + threadIdx.x;
    if (i < GG * HH) { g_sub[i] = 0.f; g_triv[i] = 0.f; g_gsum[i] = 0.f; }
    if (i < GG)       g_cnt[i] = 0.f;
    if (i < GG * 4)   g_adj[i] = 0.f;
    if (i == 0)       g_pen[0] = 0.f;
}

// Split W[K][N] (row-major) into tf32 hi/lo word arrays, SAME [K][N] layout.
__global__ __launch_bounds__(256) void wsplit(const float* __restrict__ W,
                                              uint32_t* __restrict__ dh,
                                              uint32_t* __restrict__ dl,
                                              int N) {
    int n = blockIdx.x * 256 + threadIdx.x;
    int k = blockIdx.y;
    if (n >= N) return;
    size_t idx = (size_t)k * N + n;
    float v = W[idx];
    uint32_t h = f2tf32(v);
    dh[idx] = h;
    dl[idx] = f2tf32(v - __uint_as_float(h));
}

__global__ __launch_bounds__(256) void atom_enc(const int* __restrict__ x,
                                                const float* __restrict__ aemb,
                                                const float* __restrict__ eps) {
    int n = blockIdx.x;
    int c = threadIdx.x;
    __shared__ int xs[AFEA];
    if (threadIdx.x < AFEA) xs[threadIdx.x] = x[n * AFEA + threadIdx.x];
    __syncthreads();
    float s = 0.f;
#pragma unroll
    for (int f = 0; f < AFEA; f++)
        s += aemb[((size_t)f * AVOC + xs[f]) * HH + c];
    g_h[(size_t)n * HH + c] = s;
    g_agg[(size_t)n * HH + c] = (1.f + eps[0]) * s;
}

// per-edge: agg[dst] += relu(h[src] + e_emb);  1 warp per edge (R10 proven)
__global__ __launch_bounds__(256) void edge_msg(const int* __restrict__ ei,
                                                const int* __restrict__ ea,
                                                const float* __restrict__ bemb) {
    int e = blockIdx.x * 8 + (threadIdx.x >> 5);
    if (e >= EE) return;
    int lane = threadIdx.x & 31;
    int src = ei[e], dst = ei[EE + e];
    int a0 = ea[e * 3 + 0], a1 = ea[e * 3 + 1], a2 = ea[e * 3 + 2];
    const float* b0 = bemb + (size_t)(0 * BVOC + a0) * HH;
    const float* b1 = bemb + (size_t)(1 * BVOC + a1) * HH;
    const float* b2 = bemb + (size_t)(2 * BVOC + a2) * HH;
    const float* hs = g_h + (size_t)src * HH;
    float* ag = g_agg + (size_t)dst * HH;
#pragma unroll
    for (int v = 0; v < 2; v++) {
        int c = v * 128 + lane * 4;
        float4 hv = *reinterpret_cast<const float4*>(hs + c);
        float4 e0 = *reinterpret_cast<const float4*>(b0 + c);
        float4 e1 = *reinterpret_cast<const float4*>(b1 + c);
        float4 e2 = *reinterpret_cast<const float4*>(b2 + c);
        float m0 = fmaxf(hv.x + e0.x + e1.x + e2.x, 0.f);
        float m1 = fmaxf(hv.y + e0.y + e1.y + e2.y, 0.f);
        float m2 = fmaxf(hv.z + e0.z + e1.z + e2.z, 0.f);
        float m3 = fmaxf(hv.w + e0.w + e1.w + e2.w, 0.f);
        atomicAdd(ag + c + 0, m0);
        atomicAdd(ag + c + 1, m1);
        atomicAdd(ag + c + 2, m2);
        atomicAdd(ag + c + 3, m3);
    }
}

// ---------------------------------------------------------------------------
// 3xTF32 mma.sync GEMM: C[M,Nc] = A[M,K] @ W[K,Nc].
// Block tile 128x256, BK=8, 8 warps (2m x 4n), WARP TILE 64x64 (3x less LDS
// traffic per MMA than 32x64 — the gemm is L1-throughput-bound).
// W pre-split tf32 hi/lo [K][N]; B staged via cp.async; A split in registers.
// Dynamic smem 58368 B. Epilogues: 0 BN+ReLU, 1 +bias(+agg), 2 tanh(+bias).
// ---------------------------------------------------------------------------
#define ASTR 12
#define BSTR 264
#define A_BUFW 1536        // 128*12 words per buffer
#define B_BUFW 2112        // 8*264 words per buffer
#define SM_AH  0
#define SM_AL  (2 * A_BUFW)
#define SM_BH  (4 * A_BUFW)
#define SM_BL  (4 * A_BUFW + 2 * B_BUFW)
#define SM_TOTW (4 * A_BUFW + 4 * B_BUFW)   // 14592 words = 58368 B

extern __shared__ uint32_t dsm[];

__global__ __launch_bounds__(256) void mma_gemm(
    const float* __restrict__ A, const uint32_t* __restrict__ BhG,
    const uint32_t* __restrict__ BlG, float* __restrict__ C,
    int M, int K, int Nc, int mode,
    const float* __restrict__ bias,
    const float* __restrict__ gamma, const float* __restrict__ beta,
    const float* __restrict__ mean, const float* __restrict__ var,
    const float* __restrict__ eps, int next_l, float* __restrict__ agg_out) {
    const int tid = threadIdx.x;
    const int m0 = blockIdx.x * 128, n0 = blockIdx.y * 256;
    const int lane = tid & 31, wid = tid >> 5;
    const int wm = (wid & 1) * 64;        // warp m offset (2 m-blocks)
    const int wn = (wid >> 1) * 64;       // warp n offset (4 n-blocks)
    const int g = lane >> 2, ct = lane & 3;

    // A staging: 2 threads/row, 4 floats each (128 x 8)
    const int arow = tid >> 1, acol = (tid & 1) << 2;
    const int grow = m0 + arow;
    const bool aval = grow < M;
    const float* Aptr = A + (size_t)grow * K + acol;
    // B staging: 32 threads/k-row, 8 words each (8 x 256)
    const int brow = tid >> 5, bcol = (tid & 31) << 3;
    const uint32_t* BptrH = BhG + (size_t)brow * Nc + n0 + bcol;
    const uint32_t* BptrL = BlG + (size_t)brow * Nc + n0 + bcol;

    // ---- tile 0 ----
    cp_async16(smem_u32(&dsm[SM_BH + brow * BSTR + bcol]), BptrH);
    cp_async16(smem_u32(&dsm[SM_BH + brow * BSTR + bcol + 4]), BptrH + 4);
    cp_async16(smem_u32(&dsm[SM_BL + brow * BSTR + bcol]), BptrL);
    cp_async16(smem_u32(&dsm[SM_BL + brow * BSTR + bcol + 4]), BptrL + 4);
    CP_COMMIT();
    float4 ap = aval ? *reinterpret_cast<const float4*>(Aptr)
                     : make_float4(0.f, 0.f, 0.f, 0.f);
    {
        float av[4] = {ap.x, ap.y, ap.z, ap.w};
#pragma unroll
        for (int j = 0; j < 4; j++) {
            uint32_t hi = f2tf32(av[j]);
            dsm[SM_AH + arow * ASTR + acol + j] = hi;
            dsm[SM_AL + arow * ASTR + acol + j] = f2tf32(av[j] - __uint_as_float(hi));
        }
    }
    CP_WAIT0();
    __syncthreads();

    float acc[4][8][4];
#pragma unroll
    for (int mi = 0; mi < 4; mi++)
#pragma unroll
        for (int ni = 0; ni < 8; ni++)
#pragma unroll
            for (int q = 0; q < 4; q++) acc[mi][ni][q] = 0.f;

    const int nk = K >> 3;
    int buf = 0;
    for (int kt = 0; kt < nk; kt++) {
        const int nb = buf ^ 1;
        if (kt + 1 < nk) {
            int kb = (kt + 1) << 3;
            const uint32_t* bh = BptrH + (size_t)kb * Nc;
            const uint32_t* bl = BptrL + (size_t)kb * Nc;
            cp_async16(smem_u32(&dsm[SM_BH + nb * B_BUFW + brow * BSTR + bcol]), bh);
            cp_async16(smem_u32(&dsm[SM_BH + nb * B_BUFW + brow * BSTR + bcol + 4]), bh + 4);
            cp_async16(smem_u32(&dsm[SM_BL + nb * B_BUFW + brow * BSTR + bcol]), bl);
            cp_async16(smem_u32(&dsm[SM_BL + nb * B_BUFW + brow * BSTR + bcol + 4]), bl + 4);
            CP_COMMIT();
            ap = aval ? *reinterpret_cast<const float4*>(Aptr + kb)
                      : make_float4(0.f, 0.f, 0.f, 0.f);
        }
        const uint32_t* sAh = dsm + SM_AH + buf * A_BUFW;
        const uint32_t* sAl = dsm + SM_AL + buf * A_BUFW;
        const uint32_t* sBh = dsm + SM_BH + buf * B_BUFW;
        const uint32_t* sBl = dsm + SM_BL + buf * B_BUFW;

        uint32_t ah[4][4], al[4][4];
#pragma unroll
        for (int mi = 0; mi < 4; mi++) {
            int mbase = wm + mi * 16;
#pragma unroll
            for (int q = 0; q < 4; q++) {
                int r = mbase + g + (q & 1) * 8;
                int c = ct + (q >> 1) * 4;
                ah[mi][q] = sAh[r * ASTR + c];
                al[mi][q] = sAl[r * ASTR + c];
            }
        }
#pragma unroll
        for (int ni = 0; ni < 8; ni++) {
            int nbase = wn + ni * 8 + g;
            uint32_t bh0 = sBh[ct * BSTR + nbase];
            uint32_t bh1 = sBh[(ct + 4) * BSTR + nbase];
            uint32_t bl0 = sBl[ct * BSTR + nbase];
            uint32_t bl1 = sBl[(ct + 4) * BSTR + nbase];
#pragma unroll
            for (int mi = 0; mi < 4; mi++) {
                mma_tf32(acc[mi][ni], ah[mi], bl0, bl1);   // Ah*Bl
                mma_tf32(acc[mi][ni], al[mi], bh0, bh1);   // Al*Bh
                mma_tf32(acc[mi][ni], ah[mi], bh0, bh1);   // Ah*Bh
            }
        }
        if (kt + 1 < nk) {
            float av[4] = {ap.x, ap.y, ap.z, ap.w};
#pragma unroll
            for (int j = 0; j < 4; j++) {
                uint32_t hi = f2tf32(av[j]);
                dsm[SM_AH + nb * A_BUFW + arow * ASTR + acol + j] = hi;
                dsm[SM_AL + nb * A_BUFW + arow * ASTR + acol + j] =
                    f2tf32(av[j] - __uint_as_float(hi));
            }
            CP_WAIT0();
        }
        __syncthreads();
        buf ^= 1;
    }

    // epilogue
    float aggsc = 0.f;
    if (agg_out) aggsc = 1.f + __ldg(eps + next_l);
#pragma unroll
    for (int mi = 0; mi < 4; mi++) {
#pragma unroll
        for (int half = 0; half < 2; half++) {
            int r = m0 + wm + mi * 16 + g + half * 8;
            if (r >= M) continue;
#pragma unroll
            for (int ni = 0; ni < 8; ni++) {
                int cix = n0 + wn + ni * 8 + ct * 2;
                float v0 = acc[mi][ni][half * 2 + 0];
                float v1 = acc[mi][ni][half * 2 + 1];
                if (mode == 0) {
                    float sc0 = gamma[cix + 0] * rsqrtf(var[cix + 0] + BN_EPS);
                    float sc1 = gamma[cix + 1] * rsqrtf(var[cix + 1] + BN_EPS);
                    v0 = fmaxf((v0 + bias[cix + 0] - mean[cix + 0]) * sc0 + beta[cix + 0], 0.f);
                    v1 = fmaxf((v1 + bias[cix + 1] - mean[cix + 1]) * sc1 + beta[cix + 1], 0.f);
                } else if (mode == 1) {
                    v0 += bias[cix + 0];
                    v1 += bias[cix + 1];
                } else {
                    v0 = tanhf(v0 + bias[cix + 0]);
                    v1 = tanhf(v1 + bias[cix + 1]);
                }
                *reinterpret_cast<float2*>(C + (size_t)r * Nc + cix) = make_float2(v0, v1);
                if (agg_out) {
                    *reinterpret_cast<float2*>(agg_out + (size_t)r * Nc + cix) =
                        make_float2(v0 * aggsc, v1 * aggsc);
                }
            }
        }
    }
}

// ---------------- remaining pipeline (unchanged, proven) ----------------

__global__ __launch_bounds__(256) void assign_pool(const float* __restrict__ c2W,
                                                   const float* __restrict__ c2b,
                                                   const int* __restrict__ batch,
                                                   float* __restrict__ out) {
    int n = blockIdx.x;
    int c = threadIdx.x;
    float t = g_agg[(size_t)n * HH + c];
    float2 lg = block_reduce2(t * c2W[c * 2 + 0], t * c2W[c * 2 + 1]);
    float l0 = lg.x + c2b[0], l1 = lg.y + c2b[1];
    float m = fmaxf(l0, l1);
    float e0 = expf(l0 - m), e1 = expf(l1 - m);
    float inv = 1.f / (e0 + e1);
    float a0 = e0 * inv, a1 = e1 * inv;
    float hv = g_h[(size_t)n * HH + c];
    int g = batch[n];
    atomicAdd(&g_sub[g * HH + c], a0 * hv);
    atomicAdd(&g_triv[g * HH + c], a1 * hv);
    atomicAdd(&g_gsum[g * HH + c], hv);
    if (c == 0) {
        atomicAdd(&g_cnt[g], 1.f);
        out[O_MASK + n] = (a0 > 0.5f) ? 1.f : 0.f;
        g_assign[(size_t)n * 2 + 0] = a0;
        g_assign[(size_t)n * 2 + 1] = a1;
    }
}

__global__ __launch_bounds__(256) void adj_k(const int* __restrict__ ei,
                                             const int* __restrict__ batch) {
    int e = blockIdx.x * 256 + threadIdx.x;
    if (e >= EE) return;
    int s = ei[e], d = ei[EE + e];
    int gs = batch[s], gd = batch[d];
    if (gs != gd) return;
    float as0 = g_assign[(size_t)s * 2], as1 = g_assign[(size_t)s * 2 + 1];
    float ad0 = g_assign[(size_t)d * 2], ad1 = g_assign[(size_t)d * 2 + 1];
    float* A = g_adj + gs * 4;
    atomicAdd(A + 0, as0 * ad0);
    atomicAdd(A + 1, as0 * ad1);
    atomicAdd(A + 2, as1 * ad0);
    atomicAdd(A + 3, as1 * ad1);
}

__global__ __launch_bounds__(256) void fin_pool(float* __restrict__ out) {
    int i = blockIdx.x * 256 + threadIdx.x;
    if (i >= GG * HH) return;
    int g = i / HH;
    out[O_SUB + i] = g_sub[i];
    out[O_GE + i] = g_gsum[i] / fmaxf(g_cnt[g], 1.f);
}

__global__ __launch_bounds__(256) void head_k(int which,
                                              const float* __restrict__ l1W,
                                              const float* __restrict__ l1b,
                                              const float* __restrict__ l2W,
                                              const float* __restrict__ l2b,
                                              float* __restrict__ out) {
    int g = blockIdx.x;
    int c = threadIdx.x;
    __shared__ float row[HH];
    row[c] = (which == 0) ? g_sub[(size_t)g * HH + c] : g_triv[(size_t)g * HH + c];
    __syncthreads();
    float acc = l1b[c];
#pragma unroll 4
    for (int k = 0; k < HH; k++)
        acc += row[k] * l1W[(size_t)k * HH + c];
    float z = fmaxf(acc, 0.f);
    float2 lg = block_reduce2(z * l2W[c * 2 + 0], z * l2W[c * 2 + 1]);
    if (c == 0) {
        float l0 = lg.x + l2b[0], l1 = lg.y + l2b[1];
        float m = fmaxf(l0, l1);
        float ls = logf(expf(l0 - m) + expf(l1 - m)) + m;
        out[g * 2 + 0] = l0 - ls;
        out[g * 2 + 1] = l1 - ls;
    }
}

__global__ __launch_bounds__(256) void pen_k() {
    int g = blockIdx.x * 256 + threadIdx.x;
    if (g >= GG) return;
    float a00 = g_adj[g * 4 + 0], a01 = g_adj[g * 4 + 1];
    float a10 = g_adj[g * 4 + 2], a11 = g_adj[g * 4 + 3];
    float r0 = fmaxf(fabsf(a00) + fabsf(a01), 1e-12f);
    float r1 = fmaxf(fabsf(a10) + fabsf(a11), 1e-12f);
    float d0 = a00 / r0 - 1.f, d1 = a11 / r1 - 1.f;
    atomicAdd(g_pen, d0 * d0 + d1 * d1);
}

__global__ void pen_w(float* __restrict__ out) {
    out[O_PEN] = g_pen[0] / (2.f * GG);
}

// ---------------- host launcher ----------------
extern "C" void kernel_launch(void* const* d_in, const int* in_sizes, int n_in,
                              void* d_out, int out_size) {
    int o = (n_in >= 24) ? 1 : 0;
    const int*   x     = (const int*)d_in[0];
    const int*   ei    = (const int*)d_in[1];
    const int*   ea    = (const int*)d_in[2];
    const int*   batch = (const int*)d_in[3];
    const float* aemb  = (const float*)d_in[4 + o];
    const float* bemb  = (const float*)d_in[5 + o];
    const float* eps   = (const float*)d_in[6 + o];
    const float* W1    = (const float*)d_in[7 + o];
    const float* b1    = (const float*)d_in[8 + o];
    const float* gma   = (const float*)d_in[9 + o];
    const float* bta   = (const float*)d_in[10 + o];
    const float* mu    = (const float*)d_in[11 + o];
    const float* var   = (const float*)d_in[12 + o];
    const float* W2    = (const float*)d_in[13 + o];
    const float* b2    = (const float*)d_in[14 + o];
    const float* c1W   = (const float*)d_in[15 + o];
    const float* c1b   = (const float*)d_in[16 + o];
    const float* c2W   = (const float*)d_in[17 + o];
    const float* c2b   = (const float*)d_in[18 + o];
    const float* l1W   = (const float*)d_in[19 + o];
    const float* l1b   = (const float*)d_in[20 + o];
    const float* l2W   = (const float*)d_in[21 + o];
    const float* l2b   = (const float*)d_in[22 + o];
    float* out = (float*)d_out;

    float *p_h, *p_agg, *p_z;
    uint32_t *p_wh, *p_wl;
    cudaGetSymbolAddress((void**)&p_h, g_h);
    cudaGetSymbolAddress((void**)&p_agg, g_agg);
    cudaGetSymbolAddress((void**)&p_z, g_z);
    cudaGetSymbolAddress((void**)&p_wh, g_wh);
    cudaGetSymbolAddress((void**)&p_wl, g_wl);

    const int SMEMB = SM_TOTW * 4;   // 58368 B
    cudaFuncSetAttribute(mma_gemm, cudaFuncAttributeMaxDynamicSharedMemorySize, SMEMB);

    zero_k<<<(GG * HH + 255) / 256, 256>>>();
    atom_enc<<<NN, 256>>>(x, aemb, eps);

    // pre-split weights (static per launch): W[K][N] -> tf32 hi/lo, same layout
    for (int l = 0; l < LLAY; l++) {
        wsplit<<<dim3(2, HH), 256>>>(W1 + (size_t)l * HH * H2,
                                     p_wh + WOFF_W1(l), p_wl + WOFF_W1(l), H2);
        wsplit<<<dim3(1, H2), 256>>>(W2 + (size_t)l * H2 * HH,
                                     p_wh + WOFF_W2(l), p_wl + WOFF_W2(l), HH);
    }
    wsplit<<<dim3(1, HH), 256>>>(c1W, p_wh + WOFF_C1, p_wl + WOFF_C1, HH);

    const int gmx = (NN + 127) / 128;
    for (int l = 0; l < LLAY; l++) {
        edge_msg<<<(EE + 7) / 8, 256>>>(ei, ea, bemb + (size_t)l * BFEA * BVOC * HH);
        // z = relu(BN(agg @ W1[l] + b1[l]))   [N, 512]
        mma_gemm<<<dim3(gmx, H2 / 256), 256, SMEMB>>>(p_agg,
                                                      p_wh + WOFF_W1(l), p_wl + WOFF_W1(l),
                                                      p_z, NN, HH, H2, 0,
                                                      b1 + (size_t)l * H2, gma + (size_t)l * H2,
                                                      bta + (size_t)l * H2, mu + (size_t)l * H2,
                                                      var + (size_t)l * H2,
                                                      nullptr, 0, nullptr);
        // h = z @ W2[l] + b2[l]               [N, 256]; fused agg init for next layer
        float* next_agg = (l + 1 < LLAY) ? p_agg : nullptr;
        mma_gemm<<<dim3(gmx, HH / 256), 256, SMEMB>>>(p_z,
                                                      p_wh + WOFF_W2(l), p_wl + WOFF_W2(l),
                                                      p_h, NN, H2, HH, 1,
                                                      b2 + (size_t)l * HH, nullptr, nullptr,
                                                      nullptr, nullptr,
                                                      eps, l + 1, next_agg);
    }

    // t = tanh(h @ c1W + c1b)  -> g_agg
    mma_gemm<<<dim3(gmx, HH / 256), 256, SMEMB>>>(p_h,
                                                  p_wh + WOFF_C1, p_wl + WOFF_C1,
                                                  p_agg, NN, HH, HH, 2,
                                                  c1b, nullptr, nullptr, nullptr, nullptr,
                                                  nullptr, 0, nullptr);

    assign_pool<<<NN, 256>>>(c2W, c2b, batch, out);
    adj_k<<<(EE + 255) / 256, 256>>>(ei, batch);
    fin_pool<<<(GG * HH + 255) / 256, 256>>>(out);
    head_k<<<GG, 256>>>(0, l1W, l1b, l2W, l2b, out + O_HS);
    head_k<<<GG, 256>>>(1, l1W, l1b, l2W, l2b, out + O_HT);
    pen_k<<<(GG + 255) / 256, 256>>>();
    pen_w<<<1, 1>>>(out);
    (void)in_sizes; (void)out_size;
}

// round 15
// speedup vs baseline: 1.2315x; 1.2315x over previous
#include <cuda_runtime.h>
#include <math.h>
#include <stdint.h>

#define NN   100000
#define EE   400000
#define GG   2048
#define HH   256
#define H2   512
#define LLAY 5
#define AFEA 9
#define BFEA 3
#define AVOC 128
#define BVOC 16
#define BN_EPS 1e-5f
#define NBLK 98   // ceil(NN/1024)

// Output layout (flattened float32), total 1,156,769 elements:
#define O_HS   0                      // head(sub)   [G,2]
#define O_HT   (2*GG)                 // head(triv)  [G,2]
#define O_SUB  (4*GG)                 // sub         [G,H]
#define O_GE   (4*GG + GG*HH)         // graph_emb   [G,H]
#define O_MASK (4*GG + 2*GG*HH)       // active_mask [N]
#define O_PEN  (4*GG + 2*GG*HH + NN)  // con_penalty scalar

// ---------------- scratch (device globals; no allocs allowed) ----------------
__device__ float g_h[(size_t)NN * HH];
__device__ float g_agg[(size_t)NN * HH];
__device__ float g_z[(size_t)NN * H2];
__device__ float g_assign[(size_t)NN * 2];
__device__ float g_sub[GG * HH];
__device__ float g_triv[GG * HH];
__device__ float g_gsum[GG * HH];
__device__ float g_cnt[GG];
__device__ float g_adj[GG * 4];
__device__ float g_pen[1];

// CSR by destination node (edges are launch-static)
__device__ int g_deg[NN];
__device__ int g_off[NN + 1];
__device__ int g_cur[NN];
__device__ int g_eidx[EE];
__device__ int g_part[NBLK];
__device__ int g_part2[NBLK];

// Pre-split tf32 hi/lo weights, SAME [K][N] layout as the source weights.
#define WOFF_W1(l) ((size_t)(l) * 131072)
#define WOFF_W2(l) (655360 + (size_t)(l) * 131072)
#define WOFF_C1   1310720
#define WTOT      1376256
__device__ uint32_t g_wh[WTOT];
__device__ uint32_t g_wl[WTOT];

// ---------------- small utilities ----------------
__device__ __forceinline__ float2 block_reduce2(float a, float b) {
    __shared__ float s0[8], s1[8];
    __shared__ float r0, r1;
    int wid = threadIdx.x >> 5, lane = threadIdx.x & 31;
#pragma unroll
    for (int o = 16; o > 0; o >>= 1) {
        a += __shfl_down_sync(0xffffffffu, a, o);
        b += __shfl_down_sync(0xffffffffu, b, o);
    }
    if (lane == 0) { s0[wid] = a; s1[wid] = b; }
    __syncthreads();
    if (wid == 0) {
        a = (lane < 8) ? s0[lane] : 0.f;
        b = (lane < 8) ? s1[lane] : 0.f;
#pragma unroll
        for (int o = 4; o > 0; o >>= 1) {
            a += __shfl_down_sync(0xffffffffu, a, o);
            b += __shfl_down_sync(0xffffffffu, b, o);
        }
        if (lane == 0) { r0 = a; r1 = b; }
    }
    __syncthreads();
    return make_float2(r0, r1);
}

__device__ __forceinline__ uint32_t f2tf32(float x) {
    uint32_t r;
    asm("cvt.rna.tf32.f32 %0, %1;" : "=r"(r) : "f"(x));
    return r;
}

__device__ __forceinline__ uint32_t smem_u32(const void* p) {
    uint32_t a;
    asm("{ .reg .u64 t; cvta.to.shared.u64 t, %1; cvt.u32.u64 %0, t; }" : "=r"(a) : "l"(p));
    return a;
}

__device__ __forceinline__ void cp_async16(uint32_t dst, const void* src) {
    asm volatile("cp.async.ca.shared.global [%0], [%1], 16;" :: "r"(dst), "l"(src) : "memory");
}
#define CP_COMMIT() asm volatile("cp.async.commit_group;" ::: "memory")
#define CP_WAIT0()  asm volatile("cp.async.wait_group 0;" ::: "memory")

__device__ __forceinline__ void mma_tf32(float* d, const uint32_t* a, uint32_t b0, uint32_t b1) {
    asm volatile("mma.sync.aligned.m16n8k8.row.col.f32.tf32.tf32.f32 "
                 "{%0,%1,%2,%3}, {%4,%5,%6,%7}, {%8,%9}, {%0,%1,%2,%3};"
                 : "+f"(d[0]), "+f"(d[1]), "+f"(d[2]), "+f"(d[3])
                 : "r"(a[0]), "r"(a[1]), "r"(a[2]), "r"(a[3]), "r"(b0), "r"(b1));
}

// ---------------- misc kernels ----------------

__global__ __launch_bounds__(256) void zero_k() {
    int i = blockIdx.x * 256 + threadIdx.x;
    if (i < GG * HH) { g_sub[i] = 0.f; g_triv[i] = 0.f; g_gsum[i] = 0.f; }
    if (i < GG)       g_cnt[i] = 0.f;
    if (i < GG * 4)   g_adj[i] = 0.f;
    if (i < NN)      { g_deg[i] = 0; g_cur[i] = 0; }
    if (i == 0)       g_pen[0] = 0.f;
}

// Split W[K][N] (row-major) into tf32 hi/lo word arrays, SAME [K][N] layout.
__global__ __launch_bounds__(256) void wsplit(const float* __restrict__ W,
                                              uint32_t* __restrict__ dh,
                                              uint32_t* __restrict__ dl,
                                              int N) {
    int n = blockIdx.x * 256 + threadIdx.x;
    int k = blockIdx.y;
    if (n >= N) return;
    size_t idx = (size_t)k * N + n;
    float v = W[idx];
    uint32_t h = f2tf32(v);
    dh[idx] = h;
    dl[idx] = f2tf32(v - __uint_as_float(h));
}

// ---- CSR build (once per launch; edges static) ----
__global__ __launch_bounds__(256) void count_k(const int* __restrict__ ei) {
    int e = blockIdx.x * 256 + threadIdx.x;
    if (e >= EE) return;
    atomicAdd(&g_deg[ei[EE + e]], 1);
}

__global__ __launch_bounds__(1024) void scan_blk() {
    __shared__ int s[1024];
    int n = blockIdx.x * 1024 + threadIdx.x;
    int v = (n < NN) ? g_deg[n] : 0;
    s[threadIdx.x] = v;
    __syncthreads();
    for (int o = 1; o < 1024; o <<= 1) {
        int t = (threadIdx.x >= o) ? s[threadIdx.x - o] : 0;
        __syncthreads();
        s[threadIdx.x] += t;
        __syncthreads();
    }
    if (n < NN) g_off[n] = s[threadIdx.x] - v;      // exclusive within block
    if (threadIdx.x == 1023) g_part[blockIdx.x] = s[1023];
}

__global__ void scan_top() {
    if (threadIdx.x == 0) {
        int acc = 0;
        for (int i = 0; i < NBLK; i++) { g_part2[i] = acc; acc += g_part[i]; }
    }
}

__global__ __launch_bounds__(256) void scan_add() {
    int n = blockIdx.x * 256 + threadIdx.x;
    if (n < NN) g_off[n] += g_part2[n >> 10];
    else if (n == NN) g_off[NN] = EE;
}

__global__ __launch_bounds__(256) void scatter_k(const int* __restrict__ ei) {
    int e = blockIdx.x * 256 + threadIdx.x;
    if (e >= EE) return;
    int d = ei[EE + e];
    int slot = g_off[d] + atomicAdd(&g_cur[d], 1);
    g_eidx[slot] = e;
}

// h[n][c] = sum_f atom_emb[f, x[n,f], c]
__global__ __launch_bounds__(256) void atom_enc(const int* __restrict__ x,
                                                const float* __restrict__ aemb) {
    int n = blockIdx.x;
    int c = threadIdx.x;
    __shared__ int xs[AFEA];
    if (threadIdx.x < AFEA) xs[threadIdx.x] = x[n * AFEA + threadIdx.x];
    __syncthreads();
    float s = 0.f;
#pragma unroll
    for (int f = 0; f < AFEA; f++)
        s += aemb[((size_t)f * AVOC + xs[f]) * HH + c];
    g_h[(size_t)n * HH + c] = s;
}

// Atomic-free aggregation: one warp per node; agg[n] = (1+eps)*h[n] + sum relu(h[src]+emb)
__global__ __launch_bounds__(256) void agg_k(const int* __restrict__ ei,
                                             const int* __restrict__ ea,
                                             const float* __restrict__ bemb,
                                             const float* __restrict__ eps, int l) {
    int n = blockIdx.x * 8 + (threadIdx.x >> 5);
    if (n >= NN) return;
    int lane = threadIdx.x & 31;
    int c0 = lane * 4, c1 = 128 + lane * 4;
    float sc = 1.f + __ldg(eps + l);
    const float* hn = g_h + (size_t)n * HH;
    float4 h0 = *reinterpret_cast<const float4*>(hn + c0);
    float4 h1 = *reinterpret_cast<const float4*>(hn + c1);
    float4 a0v = make_float4(sc * h0.x, sc * h0.y, sc * h0.z, sc * h0.w);
    float4 a1v = make_float4(sc * h1.x, sc * h1.y, sc * h1.z, sc * h1.w);
    int beg = g_off[n], end = g_off[n + 1];
    for (int i = beg; i < end; i++) {
        int e = g_eidx[i];
        int src = ei[e];
        int b0i = ea[e * 3 + 0], b1i = ea[e * 3 + 1], b2i = ea[e * 3 + 2];
        const float* b0 = bemb + (size_t)(0 * BVOC + b0i) * HH;
        const float* b1 = bemb + (size_t)(1 * BVOC + b1i) * HH;
        const float* b2 = bemb + (size_t)(2 * BVOC + b2i) * HH;
        const float* hs = g_h + (size_t)src * HH;
        float4 s0 = *reinterpret_cast<const float4*>(hs + c0);
        float4 s1 = *reinterpret_cast<const float4*>(hs + c1);
        float4 e00 = *reinterpret_cast<const float4*>(b0 + c0);
        float4 e01 = *reinterpret_cast<const float4*>(b0 + c1);
        float4 e10 = *reinterpret_cast<const float4*>(b1 + c0);
        float4 e11 = *reinterpret_cast<const float4*>(b1 + c1);
        float4 e20 = *reinterpret_cast<const float4*>(b2 + c0);
        float4 e21 = *reinterpret_cast<const float4*>(b2 + c1);
        a0v.x += fmaxf(s0.x + e00.x + e10.x + e20.x, 0.f);
        a0v.y += fmaxf(s0.y + e00.y + e10.y + e20.y, 0.f);
        a0v.z += fmaxf(s0.z + e00.z + e10.z + e20.z, 0.f);
        a0v.w += fmaxf(s0.w + e00.w + e10.w + e20.w, 0.f);
        a1v.x += fmaxf(s1.x + e01.x + e11.x + e21.x, 0.f);
        a1v.y += fmaxf(s1.y + e01.y + e11.y + e21.y, 0.f);
        a1v.z += fmaxf(s1.z + e01.z + e11.z + e21.z, 0.f);
        a1v.w += fmaxf(s1.w + e01.w + e11.w + e21.w, 0.f);
    }
    float* ag = g_agg + (size_t)n * HH;
    *reinterpret_cast<float4*>(ag + c0) = a0v;
    *reinterpret_cast<float4*>(ag + c1) = a1v;
}

// ---------------------------------------------------------------------------
// 3xTF32 mma.sync GEMM (R10, proven): C[M,Nc] = A[M,K] @ W[K,Nc].
// W pre-split into tf32 hi/lo [K][N]; B staged via cp.async into Bs[k][n]
// stride-136 smem. A split in registers. 128x128 tile, BK=8, 8 warps.
// ---------------------------------------------------------------------------
#define ASTR 12
#define BSTR 136
__global__ __launch_bounds__(256) void mma_gemm(
    const float* __restrict__ A, const uint32_t* __restrict__ BhG,
    const uint32_t* __restrict__ BlG, float* __restrict__ C,
    int M, int K, int Nc, int mode,
    const float* __restrict__ bias,
    const float* __restrict__ gamma, const float* __restrict__ beta,
    const float* __restrict__ mean, const float* __restrict__ var) {
    __shared__ uint32_t As_h[2][128 * ASTR];
    __shared__ uint32_t As_l[2][128 * ASTR];
    __shared__ uint32_t Bs_h[2][8 * BSTR];
    __shared__ uint32_t Bs_l[2][8 * BSTR];

    const int tid = threadIdx.x;
    const int m0 = blockIdx.x * 128, n0 = blockIdx.y * 128;
    const int lane = tid & 31, wid = tid >> 5;
    const int wm = (wid & 3) * 32;
    const int wn = (wid >> 2) * 64;
    const int g = lane >> 2, ct = lane & 3;

    const int arow = tid >> 1, acol = (tid & 1) << 2;     // A: 128 x 8
    const int brow = tid >> 5, bcol = (tid & 31) << 2;    // B: 8 x 128
    const int grow = m0 + arow;
    const bool aval = grow < M;
    const float* Aptr = A + (size_t)grow * K + acol;
    const uint32_t* BptrH = BhG + (size_t)brow * Nc + n0 + bcol;
    const uint32_t* BptrL = BlG + (size_t)brow * Nc + n0 + bcol;

    cp_async16(smem_u32(&Bs_h[0][brow * BSTR + bcol]), BptrH);
    cp_async16(smem_u32(&Bs_l[0][brow * BSTR + bcol]), BptrL);
    CP_COMMIT();
    float4 ap = aval ? *reinterpret_cast<const float4*>(Aptr)
                     : make_float4(0.f, 0.f, 0.f, 0.f);
    {
        float av[4] = {ap.x, ap.y, ap.z, ap.w};
#pragma unroll
        for (int j = 0; j < 4; j++) {
            uint32_t hi = f2tf32(av[j]);
            As_h[0][arow * ASTR + acol + j] = hi;
            As_l[0][arow * ASTR + acol + j] = f2tf32(av[j] - __uint_as_float(hi));
        }
    }
    CP_WAIT0();
    __syncthreads();

    float acc[2][8][4];
#pragma unroll
    for (int mi = 0; mi < 2; mi++)
#pragma unroll
        for (int ni = 0; ni < 8; ni++)
#pragma unroll
            for (int q = 0; q < 4; q++) acc[mi][ni][q] = 0.f;

    const int nk = K >> 3;
    int buf = 0;
    for (int kt = 0; kt < nk; kt++) {
        const int nb = buf ^ 1;
        if (kt + 1 < nk) {
            int kb = (kt + 1) << 3;
            cp_async16(smem_u32(&Bs_h[nb][brow * BSTR + bcol]), BptrH + (size_t)kb * Nc);
            cp_async16(smem_u32(&Bs_l[nb][brow * BSTR + bcol]), BptrL + (size_t)kb * Nc);
            CP_COMMIT();
            ap = aval ? *reinterpret_cast<const float4*>(Aptr + kb)
                      : make_float4(0.f, 0.f, 0.f, 0.f);
        }
        uint32_t ah[2][4], al[2][4];
#pragma unroll
        for (int mi = 0; mi < 2; mi++) {
            int mbase = wm + mi * 16;
#pragma unroll
            for (int q = 0; q < 4; q++) {
                int r = mbase + g + (q & 1) * 8;
                int c = ct + (q >> 1) * 4;
                ah[mi][q] = As_h[buf][r * ASTR + c];
                al[mi][q] = As_l[buf][r * ASTR + c];
            }
        }
#pragma unroll
        for (int ni = 0; ni < 8; ni++) {
            int nbase = wn + ni * 8 + g;
            uint32_t bh0 = Bs_h[buf][ct * BSTR + nbase];
            uint32_t bh1 = Bs_h[buf][(ct + 4) * BSTR + nbase];
            uint32_t bl0 = Bs_l[buf][ct * BSTR + nbase];
            uint32_t bl1 = Bs_l[buf][(ct + 4) * BSTR + nbase];
#pragma unroll
            for (int mi = 0; mi < 2; mi++) {
                mma_tf32(acc[mi][ni], ah[mi], bl0, bl1);   // Ah*Bl
                mma_tf32(acc[mi][ni], al[mi], bh0, bh1);   // Al*Bh
                mma_tf32(acc[mi][ni], ah[mi], bh0, bh1);   // Ah*Bh
            }
        }
        if (kt + 1 < nk) {
            float av[4] = {ap.x, ap.y, ap.z, ap.w};
#pragma unroll
            for (int j = 0; j < 4; j++) {
                uint32_t hi = f2tf32(av[j]);
                As_h[nb][arow * ASTR + acol + j] = hi;
                As_l[nb][arow * ASTR + acol + j] = f2tf32(av[j] - __uint_as_float(hi));
            }
            CP_WAIT0();
        }
        __syncthreads();
        buf ^= 1;
    }

    // epilogue
#pragma unroll
    for (int mi = 0; mi < 2; mi++) {
#pragma unroll
        for (int half = 0; half < 2; half++) {
            int r = m0 + wm + mi * 16 + g + half * 8;
            if (r >= M) continue;
#pragma unroll
            for (int ni = 0; ni < 8; ni++) {
                int cix = n0 + wn + ni * 8 + ct * 2;
                float v0 = acc[mi][ni][half * 2 + 0];
                float v1 = acc[mi][ni][half * 2 + 1];
                if (mode == 0) {
                    float sc0 = gamma[cix + 0] * rsqrtf(var[cix + 0] + BN_EPS);
                    float sc1 = gamma[cix + 1] * rsqrtf(var[cix + 1] + BN_EPS);
                    v0 = fmaxf((v0 + bias[cix + 0] - mean[cix + 0]) * sc0 + beta[cix + 0], 0.f);
                    v1 = fmaxf((v1 + bias[cix + 1] - mean[cix + 1]) * sc1 + beta[cix + 1], 0.f);
                } else if (mode == 1) {
                    v0 += bias[cix + 0];
                    v1 += bias[cix + 1];
                } else {
                    v0 = tanhf(v0 + bias[cix + 0]);
                    v1 = tanhf(v1 + bias[cix + 1]);
                }
                *reinterpret_cast<float2*>(C + (size_t)r * Nc + cix) = make_float2(v0, v1);
            }
        }
    }
}

// ---------------- remaining pipeline (unchanged, proven) ----------------

__global__ __launch_bounds__(256) void assign_pool(const float* __restrict__ c2W,
                                                   const float* __restrict__ c2b,
                                                   const int* __restrict__ batch,
                                                   float* __restrict__ out) {
    int n = blockIdx.x;
    int c = threadIdx.x;
    float t = g_agg[(size_t)n * HH + c];
    float2 lg = block_reduce2(t * c2W[c * 2 + 0], t * c2W[c * 2 + 1]);
    float l0 = lg.x + c2b[0], l1 = lg.y + c2b[1];
    float m = fmaxf(l0, l1);
    float e0 = expf(l0 - m), e1 = expf(l1 - m);
    float inv = 1.f / (e0 + e1);
    float a0 = e0 * inv, a1 = e1 * inv;
    float hv = g_h[(size_t)n * HH + c];
    int g = batch[n];
    atomicAdd(&g_sub[g * HH + c], a0 * hv);
    atomicAdd(&g_triv[g * HH + c], a1 * hv);
    atomicAdd(&g_gsum[g * HH + c], hv);
    if (c == 0) {
        atomicAdd(&g_cnt[g], 1.f);
        out[O_MASK + n] = (a0 > 0.5f) ? 1.f : 0.f;
        g_assign[(size_t)n * 2 + 0] = a0;
        g_assign[(size_t)n * 2 + 1] = a1;
    }
}

__global__ __launch_bounds__(256) void adj_k(const int* __restrict__ ei,
                                             const int* __restrict__ batch) {
    int e = blockIdx.x * 256 + threadIdx.x;
    if (e >= EE) return;
    int s = ei[e], d = ei[EE + e];
    int gs = batch[s], gd = batch[d];
    if (gs != gd) return;
    float as0 = g_assign[(size_t)s * 2], as1 = g_assign[(size_t)s * 2 + 1];
    float ad0 = g_assign[(size_t)d * 2], ad1 = g_assign[(size_t)d * 2 + 1];
    float* A = g_adj + gs * 4;
    atomicAdd(A + 0, as0 * ad0);
    atomicAdd(A + 1, as0 * ad1);
    atomicAdd(A + 2, as1 * ad0);
    atomicAdd(A + 3, as1 * ad1);
}

__global__ __launch_bounds__(256) void fin_pool(float* __restrict__ out) {
    int i = blockIdx.x * 256 + threadIdx.x;
    if (i >= GG * HH) return;
    int g = i / HH;
    out[O_SUB + i] = g_sub[i];
    out[O_GE + i] = g_gsum[i] / fmaxf(g_cnt[g], 1.f);
}

__global__ __launch_bounds__(256) void head_k(int which,
                                              const float* __restrict__ l1W,
                                              const float* __restrict__ l1b,
                                              const float* __restrict__ l2W,
                                              const float* __restrict__ l2b,
                                              float* __restrict__ out) {
    int g = blockIdx.x;
    int c = threadIdx.x;
    __shared__ float row[HH];
    row[c] = (which == 0) ? g_sub[(size_t)g * HH + c] : g_triv[(size_t)g * HH + c];
    __syncthreads();
    float acc = l1b[c];
#pragma unroll 4
    for (int k = 0; k < HH; k++)
        acc += row[k] * l1W[(size_t)k * HH + c];
    float z = fmaxf(acc, 0.f);
    float2 lg = block_reduce2(z * l2W[c * 2 + 0], z * l2W[c * 2 + 1]);
    if (c == 0) {
        float l0 = lg.x + l2b[0], l1 = lg.y + l2b[1];
        float m = fmaxf(l0, l1);
        float ls = logf(expf(l0 - m) + expf(l1 - m)) + m;
        out[g * 2 + 0] = l0 - ls;
        out[g * 2 + 1] = l1 - ls;
    }
}

__global__ __launch_bounds__(256) void pen_k() {
    int g = blockIdx.x * 256 + threadIdx.x;
    if (g >= GG) return;
    float a00 = g_adj[g * 4 + 0], a01 = g_adj[g * 4 + 1];
    float a10 = g_adj[g * 4 + 2], a11 = g_adj[g * 4 + 3];
    float r0 = fmaxf(fabsf(a00) + fabsf(a01), 1e-12f);
    float r1 = fmaxf(fabsf(a10) + fabsf(a11), 1e-12f);
    float d0 = a00 / r0 - 1.f, d1 = a11 / r1 - 1.f;
    atomicAdd(g_pen, d0 * d0 + d1 * d1);
}

__global__ void pen_w(float* __restrict__ out) {
    out[O_PEN] = g_pen[0] / (2.f * GG);
}

// ---------------- host launcher ----------------
extern "C" void kernel_launch(void* const* d_in, const int* in_sizes, int n_in,
                              void* d_out, int out_size) {
    int o = (n_in >= 24) ? 1 : 0;
    const int*   x     = (const int*)d_in[0];
    const int*   ei    = (const int*)d_in[1];
    const int*   ea    = (const int*)d_in[2];
    const int*   batch = (const int*)d_in[3];
    const float* aemb  = (const float*)d_in[4 + o];
    const float* bemb  = (const float*)d_in[5 + o];
    const float* eps   = (const float*)d_in[6 + o];
    const float* W1    = (const float*)d_in[7 + o];
    const float* b1    = (const float*)d_in[8 + o];
    const float* gma   = (const float*)d_in[9 + o];
    const float* bta   = (const float*)d_in[10 + o];
    const float* mu    = (const float*)d_in[11 + o];
    const float* var   = (const float*)d_in[12 + o];
    const float* W2    = (const float*)d_in[13 + o];
    const float* b2    = (const float*)d_in[14 + o];
    const float* c1W   = (const float*)d_in[15 + o];
    const float* c1b   = (const float*)d_in[16 + o];
    const float* c2W   = (const float*)d_in[17 + o];
    const float* c2b   = (const float*)d_in[18 + o];
    const float* l1W   = (const float*)d_in[19 + o];
    const float* l1b   = (const float*)d_in[20 + o];
    const float* l2W   = (const float*)d_in[21 + o];
    const float* l2b   = (const float*)d_in[22 + o];
    float* out = (float*)d_out;

    float *p_h, *p_agg, *p_z;
    uint32_t *p_wh, *p_wl;
    cudaGetSymbolAddress((void**)&p_h, g_h);
    cudaGetSymbolAddress((void**)&p_agg, g_agg);
    cudaGetSymbolAddress((void**)&p_z, g_z);
    cudaGetSymbolAddress((void**)&p_wh, g_wh);
    cudaGetSymbolAddress((void**)&p_wl, g_wl);

    zero_k<<<(GG * HH + 255) / 256, 256>>>();
    atom_enc<<<NN, 256>>>(x, aemb);

    // CSR build (edges are launch-static)
    count_k<<<(EE + 255) / 256, 256>>>(ei);
    scan_blk<<<NBLK, 1024>>>();
    scan_top<<<1, 32>>>();
    scan_add<<<(NN + 256) / 256, 256>>>();
    scatter_k<<<(EE + 255) / 256, 256>>>(ei);

    // pre-split weights (static per launch): W[K][N] -> tf32 hi/lo, same layout
    for (int l = 0; l < LLAY; l++) {
        wsplit<<<dim3(2, HH), 256>>>(W1 + (size_t)l * HH * H2,
                                     p_wh + WOFF_W1(l), p_wl + WOFF_W1(l), H2);
        wsplit<<<dim3(1, H2), 256>>>(W2 + (size_t)l * H2 * HH,
                                     p_wh + WOFF_W2(l), p_wl + WOFF_W2(l), HH);
    }
    wsplit<<<dim3(1, HH), 256>>>(c1W, p_wh + WOFF_C1, p_wl + WOFF_C1, HH);

    const int gmx = (NN + 127) / 128;
    for (int l = 0; l < LLAY; l++) {
        agg_k<<<(NN + 7) / 8, 256>>>(ei, ea, bemb + (size_t)l * BFEA * BVOC * HH, eps, l);
        // z = relu(BN(agg @ W1[l] + b1[l]))   [N, 512]
        mma_gemm<<<dim3(gmx, H2 / 128), 256>>>(p_agg,
                                               p_wh + WOFF_W1(l), p_wl + WOFF_W1(l),
                                               p_z, NN, HH, H2, 0,
                                               b1 + (size_t)l * H2, gma + (size_t)l * H2,
                                               bta + (size_t)l * H2, mu + (size_t)l * H2,
                                               var + (size_t)l * H2);
        // h = z @ W2[l] + b2[l]               [N, 256]
        mma_gemm<<<dim3(gmx, HH / 128), 256>>>(p_z,
                                               p_wh + WOFF_W2(l), p_wl + WOFF_W2(l),
                                               p_h, NN, H2, HH, 1,
                                               b2 + (size_t)l * HH, nullptr, nullptr,
                                               nullptr, nullptr);
    }

    // t = tanh(h @ c1W + c1b)  -> g_agg
    mma_gemm<<<dim3(gmx, HH / 128), 256>>>(p_h,
                                           p_wh + WOFF_C1, p_wl + WOFF_C1,
                                           p_agg, NN, HH, HH, 2,
                                           c1b, nullptr, nullptr, nullptr, nullptr);

    assign_pool<<<NN, 256>>>(c2W, c2b, batch, out);
    adj_k<<<(EE + 255) / 256, 256>>>(ei, batch);
    fin_pool<<<(GG * HH + 255) / 256, 256>>>(out);
    head_k<<<GG, 256>>>(0, l1W, l1b, l2W, l2b, out + O_HS);
    head_k<<<GG, 256>>>(1, l1W, l1b, l2W, l2b, out + O_HT);
    pen_k<<<(GG + 255) / 256, 256>>>();
    pen_w<<<1, 1>>>(out);
    (void)in_sizes; (void)out_size;
}

// round 17
// speedup vs baseline: 1.2523x; 1.0169x over previous
#include <cuda_runtime.h>
#include <math.h>
#include <stdint.h>

#define NN   100000
#define EE   400000
#define GG   2048
#define HH   256
#define H2   512
#define LLAY 5
#define AFEA 9
#define BFEA 3
#define AVOC 128
#define BVOC 16
#define BN_EPS 1e-5f
#define NBLK 98   // ceil(NN/1024)

// Output layout (flattened float32), total 1,156,769 elements:
#define O_HS   0                      // head(sub)   [G,2]
#define O_HT   (2*GG)                 // head(triv)  [G,2]
#define O_SUB  (4*GG)                 // sub         [G,H]
#define O_GE   (4*GG + GG*HH)         // graph_emb   [G,H]
#define O_MASK (4*GG + 2*GG*HH)       // active_mask [N]
#define O_PEN  (4*GG + 2*GG*HH + NN)  // con_penalty scalar

// ---------------- scratch (device globals; no allocs allowed) ----------------
__device__ float g_h[(size_t)NN * HH];
__device__ float g_agg[(size_t)NN * HH];
__device__ float g_z[(size_t)NN * H2];
__device__ float g_assign[(size_t)NN * 2];
__device__ float g_sub[GG * HH];
__device__ float g_triv[GG * HH];
__device__ float g_gsum[GG * HH];
__device__ float g_cnt[GG];
__device__ float g_adj[GG * 4];
__device__ float g_pen[1];

// CSR by destination node (edges are launch-static)
__device__ int g_deg[NN];
__device__ int g_off[NN + 1];
__device__ int g_cur[NN];
__device__ int g_eidx[EE];
__device__ int g_part[NBLK];
__device__ int g_part2[NBLK];

// Pre-split tf32 hi/lo weights, SAME [K][N] layout as the source weights.
#define WOFF_W1(l) ((size_t)(l) * 131072)
#define WOFF_W2(l) (655360 + (size_t)(l) * 131072)
#define WOFF_C1   1310720
#define WTOT      1376256
__device__ uint32_t g_wh[WTOT];
__device__ uint32_t g_wl[WTOT];

// Precomputed BN epilogue: v = acc*s + t
__device__ float g_bns[LLAY * H2];
__device__ float g_bnt[LLAY * H2];

// ---------------- small utilities ----------------
__device__ __forceinline__ float2 block_reduce2(float a, float b) {
    __shared__ float s0[8], s1[8];
    __shared__ float r0, r1;
    int wid = threadIdx.x >> 5, lane = threadIdx.x & 31;
#pragma unroll
    for (int o = 16; o > 0; o >>= 1) {
        a += __shfl_down_sync(0xffffffffu, a, o);
        b += __shfl_down_sync(0xffffffffu, b, o);
    }
    if (lane == 0) { s0[wid] = a; s1[wid] = b; }
    __syncthreads();
    if (wid == 0) {
        a = (lane < 8) ? s0[lane] : 0.f;
        b = (lane < 8) ? s1[lane] : 0.f;
#pragma unroll
        for (int o = 4; o > 0; o >>= 1) {
            a += __shfl_down_sync(0xffffffffu, a, o);
            b += __shfl_down_sync(0xffffffffu, b, o);
        }
        if (lane == 0) { r0 = a; r1 = b; }
    }
    __syncthreads();
    return make_float2(r0, r1);
}

__device__ __forceinline__ uint32_t f2tf32(float x) {
    uint32_t r;
    asm("cvt.rna.tf32.f32 %0, %1;" : "=r"(r) : "f"(x));
    return r;
}

__device__ __forceinline__ uint32_t smem_u32(const void* p) {
    uint32_t a;
    asm("{ .reg .u64 t; cvta.to.shared.u64 t, %1; cvt.u32.u64 %0, t; }" : "=r"(a) : "l"(p));
    return a;
}

__device__ __forceinline__ void cp_async16(uint32_t dst, const void* src) {
    asm volatile("cp.async.ca.shared.global [%0], [%1], 16;" :: "r"(dst), "l"(src) : "memory");
}
#define CP_COMMIT() asm volatile("cp.async.commit_group;" ::: "memory")
#define CP_WAIT0()  asm volatile("cp.async.wait_group 0;" ::: "memory")

__device__ __forceinline__ void mma_tf32(float* d, const uint32_t* a, uint32_t b0, uint32_t b1) {
    asm volatile("mma.sync.aligned.m16n8k8.row.col.f32.tf32.tf32.f32 "
                 "{%0,%1,%2,%3}, {%4,%5,%6,%7}, {%8,%9}, {%0,%1,%2,%3};"
                 : "+f"(d[0]), "+f"(d[1]), "+f"(d[2]), "+f"(d[3])
                 : "r"(a[0]), "r"(a[1]), "r"(a[2]), "r"(a[3]), "r"(b0), "r"(b1));
}

// ---------------- misc kernels ----------------

__global__ __launch_bounds__(256) void zero_k() {
    int i = blockIdx.x * 256 + threadIdx.x;
    if (i < GG * HH) { g_sub[i] = 0.f; g_triv[i] = 0.f; g_gsum[i] = 0.f; }
    if (i < GG)       g_cnt[i] = 0.f;
    if (i < GG * 4)   g_adj[i] = 0.f;
    if (i < NN)      { g_deg[i] = 0; g_cur[i] = 0; }
    if (i == 0)       g_pen[0] = 0.f;
}

// Split W[K][N] (row-major) into tf32 hi/lo word arrays, SAME [K][N] layout.
__global__ __launch_bounds__(256) void wsplit(const float* __restrict__ W,
                                              uint32_t* __restrict__ dh,
                                              uint32_t* __restrict__ dl,
                                              int N) {
    int n = blockIdx.x * 256 + threadIdx.x;
    int k = blockIdx.y;
    if (n >= N) return;
    size_t idx = (size_t)k * N + n;
    float v = W[idx];
    uint32_t h = f2tf32(v);
    dh[idx] = h;
    dl[idx] = f2tf32(v - __uint_as_float(h));
}

// BN fold: s = gamma*rsqrt(var+eps), t = (b1-mu)*s + beta
__global__ __launch_bounds__(256) void bnprep(const float* __restrict__ b1,
                                              const float* __restrict__ gma,
                                              const float* __restrict__ bta,
                                              const float* __restrict__ mu,
                                              const float* __restrict__ var) {
    int i = blockIdx.x * 256 + threadIdx.x;   // over LLAY*H2
    if (i >= LLAY * H2) return;
    float s = gma[i] * rsqrtf(var[i] + BN_EPS);
    g_bns[i] = s;
    g_bnt[i] = (b1[i] - mu[i]) * s + bta[i];
}

// ---- CSR build (once per launch; edges static) ----
__global__ __launch_bounds__(256) void count_k(const int* __restrict__ ei) {
    int e = blockIdx.x * 256 + threadIdx.x;
    if (e >= EE) return;
    atomicAdd(&g_deg[ei[EE + e]], 1);
}

__global__ __launch_bounds__(1024) void scan_blk() {
    __shared__ int s[1024];
    int n = blockIdx.x * 1024 + threadIdx.x;
    int v = (n < NN) ? g_deg[n] : 0;
    s[threadIdx.x] = v;
    __syncthreads();
    for (int o = 1; o < 1024; o <<= 1) {
        int t = (threadIdx.x >= o) ? s[threadIdx.x - o] : 0;
        __syncthreads();
        s[threadIdx.x] += t;
        __syncthreads();
    }
    if (n < NN) g_off[n] = s[threadIdx.x] - v;      // exclusive within block
    if (threadIdx.x == 1023) g_part[blockIdx.x] = s[1023];
}

__global__ void scan_top() {
    if (threadIdx.x == 0) {
        int acc = 0;
        for (int i = 0; i < NBLK; i++) { g_part2[i] = acc; acc += g_part[i]; }
    }
}

__global__ __launch_bounds__(256) void scan_add() {
    int n = blockIdx.x * 256 + threadIdx.x;
    if (n < NN) g_off[n] += g_part2[n >> 10];
    else if (n == NN) g_off[NN] = EE;
}

__global__ __launch_bounds__(256) void scatter_k(const int* __restrict__ ei) {
    int e = blockIdx.x * 256 + threadIdx.x;
    if (e >= EE) return;
    int d = ei[EE + e];
    int slot = g_off[d] + atomicAdd(&g_cur[d], 1);
    g_eidx[slot] = e;
}

// h[n][c] = sum_f atom_emb[f, x[n,f], c]
__global__ __launch_bounds__(256) void atom_enc(const int* __restrict__ x,
                                                const float* __restrict__ aemb) {
    int n = blockIdx.x;
    int c = threadIdx.x;
    __shared__ int xs[AFEA];
    if (threadIdx.x < AFEA) xs[threadIdx.x] = x[n * AFEA + threadIdx.x];
    __syncthreads();
    float s = 0.f;
#pragma unroll
    for (int f = 0; f < AFEA; f++)
        s += aemb[((size_t)f * AVOC + xs[f]) * HH + c];
    g_h[(size_t)n * HH + c] = s;
}

// Atomic-free aggregation: one warp per node (R15, proven)
__global__ __launch_bounds__(256) void agg_k(const int* __restrict__ ei,
                                             const int* __restrict__ ea,
                                             const float* __restrict__ bemb,
                                             const float* __restrict__ eps, int l) {
    int n = blockIdx.x * 8 + (threadIdx.x >> 5);
    if (n >= NN) return;
    int lane = threadIdx.x & 31;
    int c0 = lane * 4, c1 = 128 + lane * 4;
    float sc = 1.f + __ldg(eps + l);
    const float* hn = g_h + (size_t)n * HH;
    float4 h0 = *reinterpret_cast<const float4*>(hn + c0);
    float4 h1 = *reinterpret_cast<const float4*>(hn + c1);
    float4 a0v = make_float4(sc * h0.x, sc * h0.y, sc * h0.z, sc * h0.w);
    float4 a1v = make_float4(sc * h1.x, sc * h1.y, sc * h1.z, sc * h1.w);
    int beg = g_off[n], end = g_off[n + 1];
    for (int i = beg; i < end; i++) {
        int e = g_eidx[i];
        int src = ei[e];
        int b0i = ea[e * 3 + 0], b1i = ea[e * 3 + 1], b2i = ea[e * 3 + 2];
        const float* b0 = bemb + (size_t)(0 * BVOC + b0i) * HH;
        const float* b1 = bemb + (size_t)(1 * BVOC + b1i) * HH;
        const float* b2 = bemb + (size_t)(2 * BVOC + b2i) * HH;
        const float* hs = g_h + (size_t)src * HH;
        float4 s0 = *reinterpret_cast<const float4*>(hs + c0);
        float4 s1 = *reinterpret_cast<const float4*>(hs + c1);
        float4 e00 = *reinterpret_cast<const float4*>(b0 + c0);
        float4 e01 = *reinterpret_cast<const float4*>(b0 + c1);
        float4 e10 = *reinterpret_cast<const float4*>(b1 + c0);
        float4 e11 = *reinterpret_cast<const float4*>(b1 + c1);
        float4 e20 = *reinterpret_cast<const float4*>(b2 + c0);
        float4 e21 = *reinterpret_cast<const float4*>(b2 + c1);
        a0v.x += fmaxf(s0.x + e00.x + e10.x + e20.x, 0.f);
        a0v.y += fmaxf(s0.y + e00.y + e10.y + e20.y, 0.f);
        a0v.z += fmaxf(s0.z + e00.z + e10.z + e20.z, 0.f);
        a0v.w += fmaxf(s0.w + e00.w + e10.w + e20.w, 0.f);
        a1v.x += fmaxf(s1.x + e01.x + e11.x + e21.x, 0.f);
        a1v.y += fmaxf(s1.y + e01.y + e11.y + e21.y, 0.f);
        a1v.z += fmaxf(s1.z + e01.z + e11.z + e21.z, 0.f);
        a1v.w += fmaxf(s1.w + e01.w + e11.w + e21.w, 0.f);
    }
    float* ag = g_agg + (size_t)n * HH;
    *reinterpret_cast<float4*>(ag + c0) = a0v;
    *reinterpret_cast<float4*>(ag + c1) = a1v;
}

// ---------------------------------------------------------------------------
// 3xTF32 mma.sync GEMM, BK=16, dynamic smem (75.8KB), fixed A-split staging.
// C[M,Nc] = A[M,K] @ W[K,Nc]; W pre-split tf32 hi/lo [K][N]; B via cp.async;
// A split in registers. Block tile 128x128, 8 warps (4m x 2n), warp tile 32x64.
// A smem [row][k] stride 20 (conflict-free); B smem [k][n] stride 136.
// Epilogues: 0: relu(acc*s+t); 1: acc+bias; 2: tanh(acc+bias)
// ---------------------------------------------------------------------------
#define ASTR 20
#define BSTR 136
#define A_BUFW 2560         // 128*20
#define B_BUFW 2176         // 16*136
#define SM_AH  0
#define SM_AL  (2 * A_BUFW)
#define SM_BH  (4 * A_BUFW)
#define SM_BL  (4 * A_BUFW + 2 * B_BUFW)
#define SM_TOTW (4 * A_BUFW + 4 * B_BUFW)   // 18944 words = 75776 B

extern __shared__ uint32_t dsm[];

// split 8 floats -> hi/lo, store as 2+2 uint4 at base/base+4
__device__ __forceinline__ void split_store8(uint32_t* dh, uint32_t* dl,
                                             float4 a, float4 b) {
    uint32_t hh[8], ll[8];
    float av[8] = {a.x, a.y, a.z, a.w, b.x, b.y, b.z, b.w};
#pragma unroll
    for (int j = 0; j < 8; j++) {
        uint32_t hi = f2tf32(av[j]);
        hh[j] = hi;
        ll[j] = f2tf32(av[j] - __uint_as_float(hi));
    }
    *reinterpret_cast<uint4*>(dh) = make_uint4(hh[0], hh[1], hh[2], hh[3]);
    *reinterpret_cast<uint4*>(dh + 4) = make_uint4(hh[4], hh[5], hh[6], hh[7]);
    *reinterpret_cast<uint4*>(dl) = make_uint4(ll[0], ll[1], ll[2], ll[3]);
    *reinterpret_cast<uint4*>(dl + 4) = make_uint4(ll[4], ll[5], ll[6], ll[7]);
}

__global__ __launch_bounds__(256) void mma_gemm(
    const float* __restrict__ A, const uint32_t* __restrict__ BhG,
    const uint32_t* __restrict__ BlG, float* __restrict__ C,
    int M, int K, int Nc, int mode,
    const float* __restrict__ ep0, const float* __restrict__ ep1) {
    const int tid = threadIdx.x;
    const int m0 = blockIdx.x * 128, n0 = blockIdx.y * 128;
    const int lane = tid & 31, wid = tid >> 5;
    const int wm = (wid & 3) * 32;
    const int wn = (wid >> 2) * 64;
    const int g = lane >> 2, ct = lane & 3;

    // A staging: 2 threads/row, 8 floats each (128 x 16)
    const int arow = tid >> 1, acol = (tid & 1) << 3;
    const int grow = m0 + arow;
    const bool aval = grow < M;
    const float* Aptr = A + (size_t)grow * K + acol;
    // B staging: 16 threads/k-row, 8 words each (16 x 128)
    const int brow = tid >> 4, bcol = (tid & 15) << 3;
    const uint32_t* BptrH = BhG + (size_t)brow * Nc + n0 + bcol;
    const uint32_t* BptrL = BlG + (size_t)brow * Nc + n0 + bcol;

    const float4 z4 = make_float4(0.f, 0.f, 0.f, 0.f);

    // ---- tile 0 ----
    cp_async16(smem_u32(&dsm[SM_BH + brow * BSTR + bcol]), BptrH);
    cp_async16(smem_u32(&dsm[SM_BH + brow * BSTR + bcol + 4]), BptrH + 4);
    cp_async16(smem_u32(&dsm[SM_BL + brow * BSTR + bcol]), BptrL);
    cp_async16(smem_u32(&dsm[SM_BL + brow * BSTR + bcol + 4]), BptrL + 4);
    CP_COMMIT();
    float4 ap0 = aval ? *reinterpret_cast<const float4*>(Aptr) : z4;
    float4 ap1 = aval ? *reinterpret_cast<const float4*>(Aptr + 4) : z4;
    split_store8(&dsm[SM_AH + arow * ASTR + acol], &dsm[SM_AL + arow * ASTR + acol],
                 ap0, ap1);
    CP_WAIT0();
    __syncthreads();

    float acc[2][8][4];
#pragma unroll
    for (int mi = 0; mi < 2; mi++)
#pragma unroll
        for (int ni = 0; ni < 8; ni++)
#pragma unroll
            for (int q = 0; q < 4; q++) acc[mi][ni][q] = 0.f;

    const int nk = K >> 4;
    int buf = 0;
    for (int kt = 0; kt < nk; kt++) {
        const int nb = buf ^ 1;
        if (kt + 1 < nk) {
            int kb = (kt + 1) << 4;
            const uint32_t* bh = BptrH + (size_t)kb * Nc;
            const uint32_t* bl = BptrL + (size_t)kb * Nc;
            cp_async16(smem_u32(&dsm[SM_BH + nb * B_BUFW + brow * BSTR + bcol]), bh);
            cp_async16(smem_u32(&dsm[SM_BH + nb * B_BUFW + brow * BSTR + bcol + 4]), bh + 4);
            cp_async16(smem_u32(&dsm[SM_BL + nb * B_BUFW + brow * BSTR + bcol]), bl);
            cp_async16(smem_u32(&dsm[SM_BL + nb * B_BUFW + brow * BSTR + bcol + 4]), bl + 4);
            CP_COMMIT();
            ap0 = aval ? *reinterpret_cast<const float4*>(Aptr + kb) : z4;
            ap1 = aval ? *reinterpret_cast<const float4*>(Aptr + kb + 4) : z4;
        }
        const uint32_t* sAh = dsm + SM_AH + buf * A_BUFW;
        const uint32_t* sAl = dsm + SM_AL + buf * A_BUFW;
        const uint32_t* sBh = dsm + SM_BH + buf * B_BUFW;
        const uint32_t* sBl = dsm + SM_BL + buf * B_BUFW;

#pragma unroll
        for (int kk = 0; kk < 2; kk++) {
            uint32_t ah[2][4], al[2][4];
#pragma unroll
            for (int mi = 0; mi < 2; mi++) {
                int mbase = wm + mi * 16;
#pragma unroll
                for (int q = 0; q < 4; q++) {
                    int r = mbase + g + (q & 1) * 8;
                    int c = kk * 8 + ct + (q >> 1) * 4;
                    ah[mi][q] = sAh[r * ASTR + c];
                    al[mi][q] = sAl[r * ASTR + c];
                }
            }
#pragma unroll
            for (int ni = 0; ni < 8; ni++) {
                int nbase = wn + ni * 8 + g;
                uint32_t bh0 = sBh[(kk * 8 + ct) * BSTR + nbase];
                uint32_t bh1 = sBh[(kk * 8 + ct + 4) * BSTR + nbase];
                uint32_t bl0 = sBl[(kk * 8 + ct) * BSTR + nbase];
                uint32_t bl1 = sBl[(kk * 8 + ct + 4) * BSTR + nbase];
#pragma unroll
                for (int mi = 0; mi < 2; mi++) {
                    mma_tf32(acc[mi][ni], ah[mi], bl0, bl1);   // Ah*Bl
                    mma_tf32(acc[mi][ni], al[mi], bh0, bh1);   // Al*Bh
                    mma_tf32(acc[mi][ni], ah[mi], bh0, bh1);   // Ah*Bh
                }
            }
        }
        if (kt + 1 < nk) {
            split_store8(&dsm[SM_AH + nb * A_BUFW + arow * ASTR + acol],
                         &dsm[SM_AL + nb * A_BUFW + arow * ASTR + acol],
                         ap0, ap1);
            CP_WAIT0();
        }
        __syncthreads();
        buf ^= 1;
    }

    // epilogue
#pragma unroll
    for (int mi = 0; mi < 2; mi++) {
#pragma unroll
        for (int half = 0; half < 2; half++) {
            int r = m0 + wm + mi * 16 + g + half * 8;
            if (r >= M) continue;
#pragma unroll
            for (int ni = 0; ni < 8; ni++) {
                int cix = n0 + wn + ni * 8 + ct * 2;
                float v0 = acc[mi][ni][half * 2 + 0];
                float v1 = acc[mi][ni][half * 2 + 1];
                if (mode == 0) {
                    v0 = fmaxf(v0 * __ldg(ep0 + cix) + __ldg(ep1 + cix), 0.f);
                    v1 = fmaxf(v1 * __ldg(ep0 + cix + 1) + __ldg(ep1 + cix + 1), 0.f);
                } else if (mode == 1) {
                    v0 += __ldg(ep0 + cix);
                    v1 += __ldg(ep0 + cix + 1);
                } else {
                    v0 = tanhf(v0 + __ldg(ep0 + cix));
                    v1 = tanhf(v1 + __ldg(ep0 + cix + 1));
                }
                *reinterpret_cast<float2*>(C + (size_t)r * Nc + cix) = make_float2(v0, v1);
            }
        }
    }
}

// ---------------- remaining pipeline (unchanged, proven) ----------------

__global__ __launch_bounds__(256) void assign_pool(const float* __restrict__ c2W,
                                                   const float* __restrict__ c2b,
                                                   const int* __restrict__ batch,
                                                   float* __restrict__ out) {
    int n = blockIdx.x;
    int c = threadIdx.x;
    float t = g_agg[(size_t)n * HH + c];
    float2 lg = block_reduce2(t * c2W[c * 2 + 0], t * c2W[c * 2 + 1]);
    float l0 = lg.x + c2b[0], l1 = lg.y + c2b[1];
    float m = fmaxf(l0, l1);
    float e0 = expf(l0 - m), e1 = expf(l1 - m);
    float inv = 1.f / (e0 + e1);
    float a0 = e0 * inv, a1 = e1 * inv;
    float hv = g_h[(size_t)n * HH + c];
    int g = batch[n];
    atomicAdd(&g_sub[g * HH + c], a0 * hv);
    atomicAdd(&g_triv[g * HH + c], a1 * hv);
    atomicAdd(&g_gsum[g * HH + c], hv);
    if (c == 0) {
        atomicAdd(&g_cnt[g], 1.f);
        out[O_MASK + n] = (a0 > 0.5f) ? 1.f : 0.f;
        g_assign[(size_t)n * 2 + 0] = a0;
        g_assign[(size_t)n * 2 + 1] = a1;
    }
}

__global__ __launch_bounds__(256) void adj_k(const int* __restrict__ ei,
                                             const int* __restrict__ batch) {
    int e = blockIdx.x * 256 + threadIdx.x;
    if (e >= EE) return;
    int s = ei[e], d = ei[EE + e];
    int gs = batch[s], gd = batch[d];
    if (gs != gd) return;
    float as0 = g_assign[(size_t)s * 2], as1 = g_assign[(size_t)s * 2 + 1];
    float ad0 = g_assign[(size_t)d * 2], ad1 = g_assign[(size_t)d * 2 + 1];
    float* A = g_adj + gs * 4;
    atomicAdd(A + 0, as0 * ad0);
    atomicAdd(A + 1, as0 * ad1);
    atomicAdd(A + 2, as1 * ad0);
    atomicAdd(A + 3, as1 * ad1);
}

__global__ __launch_bounds__(256) void fin_pool(float* __restrict__ out) {
    int i = blockIdx.x * 256 + threadIdx.x;
    if (i >= GG * HH) return;
    int g = i / HH;
    out[O_SUB + i] = g_sub[i];
    out[O_GE + i] = g_gsum[i] / fmaxf(g_cnt[g], 1.f);
}

__global__ __launch_bounds__(256) void head_k(int which,
                                              const float* __restrict__ l1W,
                                              const float* __restrict__ l1b,
                                              const float* __restrict__ l2W,
                                              const float* __restrict__ l2b,
                                              float* __restrict__ out) {
    int g = blockIdx.x;
    int c = threadIdx.x;
    __shared__ float row[HH];
    row[c] = (which == 0) ? g_sub[(size_t)g * HH + c] : g_triv[(size_t)g * HH + c];
    __syncthreads();
    float acc = l1b[c];
#pragma unroll 4
    for (int k = 0; k < HH; k++)
        acc += row[k] * l1W[(size_t)k * HH + c];
    float z = fmaxf(acc, 0.f);
    float2 lg = block_reduce2(z * l2W[c * 2 + 0], z * l2W[c * 2 + 1]);
    if (c == 0) {
        float l0 = lg.x + l2b[0], l1 = lg.y + l2b[1];
        float m = fmaxf(l0, l1);
        float ls = logf(expf(l0 - m) + expf(l1 - m)) + m;
        out[g * 2 + 0] = l0 - ls;
        out[g * 2 + 1] = l1 - ls;
    }
}

__global__ __launch_bounds__(256) void pen_k() {
    int g = blockIdx.x * 256 + threadIdx.x;
    if (g >= GG) return;
    float a00 = g_adj[g * 4 + 0], a01 = g_adj[g * 4 + 1];
    float a10 = g_adj[g * 4 + 2], a11 = g_adj[g * 4 + 3];
    float r0 = fmaxf(fabsf(a00) + fabsf(a01), 1e-12f);
    float r1 = fmaxf(fabsf(a10) + fabsf(a11), 1e-12f);
    float d0 = a00 / r0 - 1.f, d1 = a11 / r1 - 1.f;
    atomicAdd(g_pen, d0 * d0 + d1 * d1);
}

__global__ void pen_w(float* __restrict__ out) {
    out[O_PEN] = g_pen[0] / (2.f * GG);
}

// ---------------- host launcher ----------------
extern "C" void kernel_launch(void* const* d_in, const int* in_sizes, int n_in,
                              void* d_out, int out_size) {
    int o = (n_in >= 24) ? 1 : 0;
    const int*   x     = (const int*)d_in[0];
    const int*   ei    = (const int*)d_in[1];
    const int*   ea    = (const int*)d_in[2];
    const int*   batch = (const int*)d_in[3];
    const float* aemb  = (const float*)d_in[4 + o];
    const float* bemb  = (const float*)d_in[5 + o];
    const float* eps   = (const float*)d_in[6 + o];
    const float* W1    = (const float*)d_in[7 + o];
    const float* b1    = (const float*)d_in[8 + o];
    const float* gma   = (const float*)d_in[9 + o];
    const float* bta   = (const float*)d_in[10 + o];
    const float* mu    = (const float*)d_in[11 + o];
    const float* var   = (const float*)d_in[12 + o];
    const float* W2    = (const float*)d_in[13 + o];
    const float* b2    = (const float*)d_in[14 + o];
    const float* c1W   = (const float*)d_in[15 + o];
    const float* c1b   = (const float*)d_in[16 + o];
    const float* c2W   = (const float*)d_in[17 + o];
    const float* c2b   = (const float*)d_in[18 + o];
    const float* l1W   = (const float*)d_in[19 + o];
    const float* l1b   = (const float*)d_in[20 + o];
    const float* l2W   = (const float*)d_in[21 + o];
    const float* l2b   = (const float*)d_in[22 + o];
    float* out = (float*)d_out;

    float *p_h, *p_agg, *p_z, *p_bns, *p_bnt;
    uint32_t *p_wh, *p_wl;
    cudaGetSymbolAddress((void**)&p_h, g_h);
    cudaGetSymbolAddress((void**)&p_agg, g_agg);
    cudaGetSymbolAddress((void**)&p_z, g_z);
    cudaGetSymbolAddress((void**)&p_wh, g_wh);
    cudaGetSymbolAddress((void**)&p_wl, g_wl);
    cudaGetSymbolAddress((void**)&p_bns, g_bns);
    cudaGetSymbolAddress((void**)&p_bnt, g_bnt);

    const int SMEMB = SM_TOTW * 4;   // 75776 B
    cudaFuncSetAttribute(mma_gemm, cudaFuncAttributeMaxDynamicSharedMemorySize, SMEMB);

    zero_k<<<(GG * HH + 255) / 256, 256>>>();
    atom_enc<<<NN, 256>>>(x, aemb);

    // CSR build (edges are launch-static)
    count_k<<<(EE + 255) / 256, 256>>>(ei);
    scan_blk<<<NBLK, 1024>>>();
    scan_top<<<1, 32>>>();
    scan_add<<<(NN + 256) / 256, 256>>>();
    scatter_k<<<(EE + 255) / 256, 256>>>(ei);

    // pre-split weights + BN fold (static per launch)
    for (int l = 0; l < LLAY; l++) {
        wsplit<<<dim3(2, HH), 256>>>(W1 + (size_t)l * HH * H2,
                                     p_wh + WOFF_W1(l), p_wl + WOFF_W1(l), H2);
        wsplit<<<dim3(1, H2), 256>>>(W2 + (size_t)l * H2 * HH,
                                     p_wh + WOFF_W2(l), p_wl + WOFF_W2(l), HH);
    }
    wsplit<<<dim3(1, HH), 256>>>(c1W, p_wh + WOFF_C1, p_wl + WOFF_C1, HH);
    bnprep<<<(LLAY * H2 + 255) / 256, 256>>>(b1, gma, bta, mu, var);

    const int gmx = (NN + 127) / 128;
    for (int l = 0; l < LLAY; l++) {
        agg_k<<<(NN + 7) / 8, 256>>>(ei, ea, bemb + (size_t)l * BFEA * BVOC * HH, eps, l);
        // z = relu(BN(agg @ W1[l] + b1[l]))   [N, 512]
        mma_gemm<<<dim3(gmx, H2 / 128), 256, SMEMB>>>(p_agg,
                                                      p_wh + WOFF_W1(l), p_wl + WOFF_W1(l),
                                                      p_z, NN, HH, H2, 0,
                                                      p_bns + l * H2, p_bnt + l * H2);
        // h = z @ W2[l] + b2[l]               [N, 256]
        mma_gemm<<<dim3(gmx, HH / 128), 256, SMEMB>>>(p_z,
                                                      p_wh + WOFF_W2(l), p_wl + WOFF_W2(l),
                                                      p_h, NN, H2, HH, 1,
                                                      b2 + (size_t)l * HH, nullptr);
    }

    // t = tanh(h @ c1W + c1b)  -> g_agg
    mma_gemm<<<dim3(gmx, HH / 128), 256, SMEMB>>>(p_h,
                                                  p_wh + WOFF_C1, p_wl + WOFF_C1,
                                                  p_agg, NN, HH, HH, 2,
                                                  c1b, nullptr);

    assign_pool<<<NN, 256>>>(c2W, c2b, batch, out);
    adj_k<<<(EE + 255) / 256, 256>>>(ei, batch);
    fin_pool<<<(GG * HH + 255) / 256, 256>>>(out);
    head_k<<<GG, 256>>>(0, l1W, l1b, l2W, l2b, out + O_HS);
    head_k<<<GG, 256>>>(1, l1W, l1b, l2W, l2b, out + O_HT);
    pen_k<<<(GG + 255) / 256, 256>>>();
    pen_w<<<1, 1>>>(out);
    (void)in_sizes; (void)out_size;
}